// round 15
// baseline (speedup 1.0000x reference)
#include <cuda_runtime.h>
#include <cuda_fp16.h>
#include <math.h>
#include <stdint.h>

// ---------------------------------------------------------------------------
// GatedBlock via mma.sync fp16 implicit GEMM (single-term):
//   D = x_f16 * w_f16 ;  conv3d(72->176,k5,pad2) => D[M=128, N=176], K=72*128
//   gate fused into the GEMM epilogue; depthwise gaussian stride-2 fused as
//   work-stealing tail blocks in the SAME kernel (hidden in the conv tail).
// Round 15: conv = round-14 state; lowpass blocks appended to the conv grid,
//   gated by per-batch completion counters (reset by prep_kernel each replay).
// ---------------------------------------------------------------------------

#define B_      4
#define CI_     72
#define CO_     176
#define NSP_    (32*32*32)
#define NCH_    144

#define KC_     64
#define NCHUNK_ 144           // 72*128 / 64
#define A_TILE  16384         // 128 rows x 64 fp16
#define B_TILE  22528         // 176 rows x 64 fp16
#define NT_     256

#define NCONV_BLK 1024
#define NLP_ITEMS 2304        // 4 b * 144 c * 4 zt

__device__ float  g_z[(size_t)B_ * NCH_ * NSP_];
__device__ __half g_wprep[(size_t)NCHUNK_ * CO_ * KC_];  // fp16, pre-swizzled
__device__ __half g_xh[(size_t)B_ * CI_ * NSP_];         // fp16 x image
__device__ unsigned g_done[B_];                          // conv CTAs done per b
__device__ unsigned g_ticket;                            // lowpass work queue

// ---- smem byte offsets (dynamic smem, conv path) ----
// [0, 92928) reused by epilogue sD[176][132]; persistent data above it.
// lowpass path uses [0, 55440) as sZ[11][35][36].
#define SA_OFF    0                        // A: 2 x 16384 = 32768
#define SB_OFF    32768                    // B: 2 x 22528 -> 77824
#define SX_OFF    92928                    // xs: 1584 halves -> 96096
#define XS_VALS   1584
#define ST_OFF    96128                    // tapoff: 128 ints -> 96640
#define SSB_OFF   96640
#define SGB_OFF   96704
#define SMEM_TOTAL 96832

// ---------------- helpers ----------------
__device__ __forceinline__ uint32_t smem_u32(const void* p){
    uint32_t a;
    asm("{ .reg .u64 t; cvta.to.shared.u64 t, %1; cvt.u32.u64 %0, t; }"
        : "=r"(a) : "l"(p));
    return a;
}
__device__ __forceinline__ uint32_t swz(uint32_t o){
    return o ^ (((o >> 7) & 7u) << 4);
}

#define CPA16(d,s) asm volatile("cp.async.cg.shared.global [%0], [%1], 16;" :: "r"(d), "l"(s))
#define CPA4(d,s)  asm volatile("cp.async.ca.shared.global [%0], [%1], 4;"  :: "r"(d), "l"(s))
#define CPC()      asm volatile("cp.async.commit_group;")
#define CPW0()     asm volatile("cp.async.wait_group 0;")

#define LDM4(r, a) \
    asm volatile("ldmatrix.sync.aligned.m8n8.x4.shared.b16 {%0,%1,%2,%3}, [%4];" \
        : "=r"((r)[0]),"=r"((r)[1]),"=r"((r)[2]),"=r"((r)[3]) : "r"(a))
#define LDM2(r, a) \
    asm volatile("ldmatrix.sync.aligned.m8n8.x2.shared.b16 {%0,%1}, [%2];" \
        : "=r"((r)[0]),"=r"((r)[1]) : "r"(a))

#define MMAF16(d, a, b0v, b1v) \
    asm volatile("mma.sync.aligned.m16n8k16.row.col.f32.f16.f16.f32 " \
        "{%0,%1,%2,%3}, {%4,%5,%6,%7}, {%8,%9}, {%0,%1,%2,%3};" \
        : "+f"((d)[0]),"+f"((d)[1]),"+f"((d)[2]),"+f"((d)[3]) \
        : "r"((a)[0]),"r"((a)[1]),"r"((a)[2]),"r"((a)[3]), "r"(b0v), "r"(b1v))

// ---------------------------------------------------------------------------
// Weight prep: reorder to K=(ci*128+tap), fp16, pre-apply the XOR swizzle.
// Block 0 also resets the work-queue counters (runs before conv every replay).
// ---------------------------------------------------------------------------
__global__ void prep_kernel(const float* __restrict__ W)
{
    if (blockIdx.x == 0 && threadIdx.x < 5) {
        if (threadIdx.x < 4) g_done[threadIdx.x] = 0u;
        else                 g_ticket = 0u;
    }
    int e = blockIdx.x * 256 + threadIdx.x;   // 144*176*64 = 1,622,016 exact
    int col   = e & 63;
    int row   = (e >> 6) % CO_;
    int chunk = e / (CO_ * KC_);
    int k  = chunk * KC_ + col;
    int ci = k >> 7;
    int tap = k & 127;
    float v = (tap < 125) ? W[((size_t)row * CI_ + ci) * 125 + tap] : 0.f;
    uint32_t off = (uint32_t)(row * 128 + col * 2);
    uint32_t sw  = off ^ ((uint32_t)(row & 7) << 4);
    g_wprep[(size_t)chunk * (CO_ * KC_) + (sw >> 1)] = __float2half_rn(v);
}

__global__ void prep_x_kernel(const float* __restrict__ x)
{
    size_t i = (size_t)blockIdx.x * 256 + threadIdx.x;   // 9,437,184 exact
    g_xh[i] = __float2half_rn(x[i]);
}

// ---------------------------------------------------------------------------
// Lowpass device body (round-13 version): one (b, c, zt) item.
// ---------------------------------------------------------------------------
__device__ void lowpass_item(float* sZ, const float* sWg, float* __restrict__ out,
                             int b, int c, int zt, int tid)
{
    const int wrp = tid >> 5;
    const int lidl = tid & 31;
    const int zo0 = 4 * zt;
    const int zi0 = 2 * zo0 - 2;
    const float* zc = g_z + (size_t)(b * NCH_ + c) * NSP_;

    {
        int zi = 0, yi = wrp;
        for (int r = wrp; r < 385; r += 8) {
            int gz = zi0 + zi;
            int gy = yi - 2;
            bool rowok = ((unsigned)gz < 32u) & ((unsigned)gy < 32u);
            const float* rowp = zc + (gz * 32 + gy) * 32;
            float* srow = sZ + (zi * 35 + yi) * 36;
            float v = 0.f;
            int gx = lidl - 2;
            if (rowok & ((unsigned)gx < 32u)) v = rowp[gx];
            srow[lidl] = v;
            if (lidl < 3) {
                float v2 = 0.f;
                int gx2 = lidl + 30;
                if (rowok & ((unsigned)gx2 < 32u)) v2 = rowp[gx2];
                srow[32 + lidl] = v2;
            }
            yi += 8; if (yi >= 35) { yi -= 35; zi += 1; }
        }
    }
    __syncthreads();

    const int xo = tid & 15;
    const int yo = tid >> 4;
    const float* bp = sZ + (2 * yo) * 36 + 2 * xo;

    float a0 = 0.f, a1 = 0.f, a2 = 0.f, a3 = 0.f;
#pragma unroll
    for (int kh = 0; kh < 5; ++kh) {
#pragma unroll
        for (int kw = 0; kw < 5; ++kw) {
            float w0 = sWg[(0 * 5 + kh) * 5 + kw];
            float w1 = sWg[(1 * 5 + kh) * 5 + kw];
            float w2 = sWg[(2 * 5 + kh) * 5 + kw];
            float w3 = sWg[(3 * 5 + kh) * 5 + kw];
            float w4 = sWg[(4 * 5 + kh) * 5 + kw];
            const int eo = kh * 36 + kw;
#pragma unroll
            for (int p = 0; p < 11; ++p) {
                float v = bp[p * 1260 + eo];
                if (p < 5) {
                    float w = (p == 0) ? w0 : (p == 1) ? w1 : (p == 2) ? w2
                            : (p == 3) ? w3 : w4;
                    a0 += w * v;
                }
                if (p - 2 >= 0 && p - 2 < 5) {
                    int kd = p - 2;
                    float w = (kd == 0) ? w0 : (kd == 1) ? w1 : (kd == 2) ? w2
                            : (kd == 3) ? w3 : w4;
                    a1 += w * v;
                }
                if (p - 4 >= 0 && p - 4 < 5) {
                    int kd = p - 4;
                    float w = (kd == 0) ? w0 : (kd == 1) ? w1 : (kd == 2) ? w2
                            : (kd == 3) ? w3 : w4;
                    a2 += w * v;
                }
                if (p - 6 >= 0) {
                    int kd = p - 6;
                    float w = (kd == 0) ? w0 : (kd == 1) ? w1 : (kd == 2) ? w2
                            : (kd == 3) ? w3 : w4;
                    a3 += w * v;
                }
            }
        }
    }

    float* ob = out + ((size_t)(b * NCH_ + c) * 16 + zo0) * 256 + yo * 16 + xo;
    ob[0]   = a0;
    ob[256] = a1;
    ob[512] = a2;
    ob[768] = a3;
}

// ---------------------------------------------------------------------------
// Fused kernel: blocks [0,1024) = conv tiles; blocks >= 1024 = lowpass
// work-stealers (gated on per-batch conv completion).
// ---------------------------------------------------------------------------
__global__ __launch_bounds__(NT_, 2)
void conv_mma_kernel(const float* __restrict__ sbg, const float* __restrict__ gbg,
                     float* __restrict__ out)
{
    extern __shared__ unsigned char smem[];
    const int tid = threadIdx.x;

    // =================== LOWPASS ROLE ===================
    if (blockIdx.x >= NCONV_BLK) {
        __shared__ float sWg[125];
        __shared__ unsigned s_item;
        float* sZ = (float*)smem;

        if (tid < 125) {
            int kw = tid % 5, t = tid / 5;
            int kh = t % 5,  kd = t / 5;
            double g[5], s = 0.0;
#pragma unroll
            for (int r = 0; r < 5; ++r) {
                double d = (double)(r - 2);
                g[r] = exp(-d * d / 1.5);
                s += g[r];
            }
            sWg[tid] = (float)(g[kd] * g[kh] * g[kw] / (s * s * s));
        }
        __syncthreads();

        for (;;) {
            if (tid == 0) s_item = atomicAdd(&g_ticket, 1u);
            __syncthreads();
            unsigned it = s_item;
            if (it >= NLP_ITEMS) return;
            int b  = it / (NCH_ * 4);
            int r  = it % (NCH_ * 4);
            int c  = r >> 2;
            int zt = r & 3;
            if (tid == 0) {
                while (atomicAdd(&g_done[b], 0u) < 256u) __nanosleep(256);
            }
            __syncthreads();
            __threadfence();
            lowpass_item(sZ, sWg, out, b, c, zt, tid);
            __syncthreads();
        }
    }

    // =================== CONV ROLE ===================
    const uint32_t smb = smem_u32(smem);
    const int wid = tid >> 5;
    const int lid = tid & 31;
    const int bid = blockIdx.x;
    const int b  = bid >> 8;
    const int z0 = (bid >> 3) & 31;
    const int y0 = (bid & 7) * 4;

    // builder role: 8 warps = 4 y-groups x 2 k-halves (32 k each)
    const int byy = wid & 3, bkh = wid >> 2;
    // mma role: 4 M-groups x 2 N-halves
    const int m0 = (wid >> 1) * 32;
    const int n0 = (wid & 1) * 88;

    __half* xs    = (__half*)(smem + SX_OFF);
    int*   tapoff = (int*)(smem + ST_OFF);
    float* sS     = (float*)(smem + SSB_OFF);
    float* sG     = (float*)(smem + SGB_OFF);

    for (int i = tid; i < XS_VALS; i += NT_) xs[i] = __ushort_as_half(0);
    if (tid < 128) {
        int tap = tid;
        int kd = tap / 25, r = tap % 25;
        int kh = r / 5, kw = r % 5;
        tapoff[tid] = (tap < 125) ? (kd * 8 + kh) * 36 + kw : 1440;
    }
    if (tid < 16) sS[tid] = sbg[tid];
    if (tid < 32) sG[tid] = gbg[tid];
    __syncthreads();

    const __half* xb = g_xh + (size_t)b * CI_ * NSP_;

    auto stage_x = [&](int ci) {
        const __half* xc = xb + (size_t)ci * NSP_;
        for (int it = tid; it < 640; it += NT_) {
            int ck = it & 15;
            int row = it >> 4;           // zi*8 + yi
            int yi = row & 7, zi = row >> 3;
            int gy = y0 + yi - 2, gz = z0 + zi - 2;
            if ((unsigned)gy < 32u && (unsigned)gz < 32u)
                CPA4(smb + SX_OFF + (uint32_t)(row * 36 + 2 + ck * 2) * 2,
                     xc + ((gz * 32 + gy) * 32 + ck * 2));
        }
    };
    auto stage_B = [&](int n, int nb) {
        const char* src = (const char*)g_wprep + (size_t)n * B_TILE;
        uint32_t dst = smb + SB_OFF + nb * B_TILE;
        for (int i = tid; i < B_TILE / 16; i += NT_)
            CPA16(dst + i * 16, src + i * 16);
    };
    auto build_A = [&](int n, int nb) {
        char* Abase = (char*)smem + SA_OFF + nb * A_TILE;
        const int tb  = (n & 1) * 64;
        const int lin = byy * 36 + lid;
        const int m   = byy * 32 + lid;
        const uint32_t mx = (uint32_t)(m & 7) << 4;
#pragma unroll
        for (int j = 0; j < 16; ++j) {
            int k0 = bkh * 32 + 2 * j;
            uint32_t t0 = *(const unsigned short*)((const char*)xs +
                              (uint32_t)(tapoff[tb + k0]     + lin) * 2);
            uint32_t t1 = *(const unsigned short*)((const char*)xs +
                              (uint32_t)(tapoff[tb + k0 + 1] + lin) * 2);
            uint32_t hp = t0 | (t1 << 16);
            *(uint32_t*)(Abase + (((uint32_t)(m * 128 + k0 * 2)) ^ mx)) = hp;
        }
    };

    // lane-invariant ldmatrix offsets
    const uint32_t aLane  = (uint32_t)((lid & 15) * 128 + ((lid & 16) ? 16 : 0));
    const uint32_t bLane4 = (uint32_t)((((lid & 7) + ((lid & 16) ? 8 : 0)) * 128) +
                                       ((lid & 8) ? 16 : 0));
    const uint32_t bLane2 = (uint32_t)((lid & 7) * 128 + ((lid & 8) ? 16 : 0));

    float acc[2][11][4];
#pragma unroll
    for (int mi = 0; mi < 2; ++mi)
#pragma unroll
        for (int ni = 0; ni < 11; ++ni)
#pragma unroll
            for (int r = 0; r < 4; ++r) acc[mi][ni][r] = 0.f;

    // ---- prologue ----
    stage_B(0, 0);
    stage_x(0);
    CPC(); CPW0();
    __syncthreads();
    build_A(0, 0);
    __syncthreads();

    for (int c = 0; c < NCHUNK_; ++c) {
        const int bsel = c & 1;
        if (c + 1 < NCHUNK_) {
            stage_B(c + 1, bsel ^ 1);
            if (((c + 1) & 1) == 0) stage_x((c + 1) >> 1);
            CPC();
        }

        const uint32_t AhB = smb + SA_OFF + bsel * A_TILE;
        const uint32_t BhB = smb + SB_OFF + bsel * B_TILE;

#pragma unroll
        for (int ks = 0; ks < 4; ++ks) {
            const uint32_t kso = (uint32_t)ks * 32;
            uint32_t a0[4], a1[4];
            LDM4(a0, AhB + swz((uint32_t)(m0      * 128) + kso + aLane));
            LDM4(a1, AhB + swz((uint32_t)((m0+16) * 128) + kso + aLane));
#pragma unroll
            for (int nip = 0; nip < 5; ++nip) {
                uint32_t bh[4];
                LDM4(bh, BhB + swz((uint32_t)((n0 + nip * 16) * 128) + kso + bLane4));
                MMAF16(acc[0][nip * 2],     a0, bh[0], bh[1]);
                MMAF16(acc[1][nip * 2],     a1, bh[0], bh[1]);
                MMAF16(acc[0][nip * 2 + 1], a0, bh[2], bh[3]);
                MMAF16(acc[1][nip * 2 + 1], a1, bh[2], bh[3]);
            }
            {   // n-group 10 (cols 80..87)
                uint32_t b2[2];
                LDM2(b2, BhB + swz((uint32_t)((n0 + 80) * 128) + kso + bLane2));
                MMAF16(acc[0][10], a0, b2[0], b2[1]);
                MMAF16(acc[1][10], a1, b2[0], b2[1]);
            }
        }

        if (c + 1 < NCHUNK_) {
            CPW0();
            __syncthreads();
            build_A(c + 1, bsel ^ 1);
        }
        __syncthreads();
    }

    // ---- epilogue: accums -> smem, sigmoid gates, gated write to g_z ----
    float* sD = (float*)smem;   // [176][132] floats = 92928B, reuses tile smem
#pragma unroll
    for (int mi = 0; mi < 2; ++mi)
#pragma unroll
        for (int ni = 0; ni < 11; ++ni)
#pragma unroll
            for (int r = 0; r < 4; ++r) {
                int m  = m0 + mi * 16 + (lid >> 2) + ((r & 2) ? 8 : 0);
                int cc = n0 + ni * 8 + (lid & 3) * 2 + (r & 1);
                sD[cc * 132 + m] = acc[mi][ni][r];
            }
    __syncthreads();

    for (int i = tid; i < 32 * 128; i += NT_) {
        int gi = i >> 7, mm = i & 127;
        int ad = (144 + gi) * 132 + mm;
        sD[ad] = 1.f / (1.f + expf(-(sD[ad] + sG[gi])));
    }
    __syncthreads();

    float* zb = g_z + (size_t)b * NCH_ * NSP_ + (size_t)z0 * 1024 + y0 * 32;
    for (int i = tid; i < 144 * 128; i += NT_) {
        int cc = i >> 7, mm = i & 127;
        float v = sD[cc * 132 + mm];
        float o;
        if (cc < 16) o = fmaxf(v + sS[cc], 0.f);
        else {
            int gi = (cc < 64) ? (cc - 16) / 3 : 16 + (cc - 64) / 5;
            o = v * sD[(144 + gi) * 132 + mm];
        }
        zb[(size_t)cc * NSP_ + mm] = o;
    }

    // ---- signal completion for this batch ----
    __syncthreads();
    __threadfence();
    if (tid == 0) atomicAdd(&g_done[b], 1u);
}

// ---------------------------------------------------------------------------
extern "C" void kernel_launch(void* const* d_in, const int* in_sizes, int n_in,
                              void* d_out, int out_size)
{
    const float* x  = (const float*)d_in[0];   // (4,72,32,32,32)
    const float* W  = (const float*)d_in[1];   // (176,72,5,5,5)
    const float* sb = (const float*)d_in[2];   // (16,)
    const float* gb = (const float*)d_in[3];   // (32,)
    float* out = (float*)d_out;                // (4,144,16,16,16)

    cudaFuncSetAttribute(conv_mma_kernel,
                         cudaFuncAttributeMaxDynamicSharedMemorySize, SMEM_TOTAL);

    prep_kernel<<<6336, 256>>>(W);
    prep_x_kernel<<<36864, 256>>>(x);
    conv_mma_kernel<<<NCONV_BLK + NLP_ITEMS, NT_, SMEM_TOTAL>>>(sb, gb, out);
}

// round 16
// speedup vs baseline: 1.3586x; 1.3586x over previous
#include <cuda_runtime.h>
#include <cuda_fp16.h>
#include <math.h>
#include <stdint.h>

// ---------------------------------------------------------------------------
// GatedBlock via mma.sync fp16 implicit GEMM (single-term):
//   D = x_f16 * w_f16 ;  conv3d(72->176,k5,pad2) => D[M=128, N=176], K=72*128
//   gate fused into the GEMM epilogue, then depthwise gaussian stride-2.
// Round 16: conv = round-14 state (2 CTA/SM, KC=64). Lowpass: unrolled
//   independent-iteration load (MLP~8), 53.9KB smem (no pad) for 3-4 CTA/SM.
// ---------------------------------------------------------------------------

#define B_      4
#define CI_     72
#define CO_     176
#define NSP_    (32*32*32)
#define NCH_    144

#define KC_     64
#define NCHUNK_ 144           // 72*128 / 64
#define A_TILE  16384         // 128 rows x 64 fp16
#define B_TILE  22528         // 176 rows x 64 fp16
#define NT_     256

__device__ float  g_z[(size_t)B_ * NCH_ * NSP_];
__device__ __half g_wprep[(size_t)NCHUNK_ * CO_ * KC_];  // fp16, pre-swizzled
__device__ __half g_xh[(size_t)B_ * CI_ * NSP_];         // fp16 x image

// ---- smem byte offsets (dynamic smem, conv kernel) ----
// [0, 92928) reused by epilogue sD[176][132]; persistent data above it.
#define SA_OFF    0                        // A: 2 x 16384 = 32768
#define SB_OFF    32768                    // B: 2 x 22528 -> 77824
#define SX_OFF    92928                    // xs: 1584 halves -> 96096
#define XS_VALS   1584
#define ST_OFF    96128                    // tapoff: 128 ints -> 96640
#define SSB_OFF   96640
#define SGB_OFF   96704
#define SMEM_TOTAL 96832

// ---- lowpass: dynamic smem sZ[385][35] floats (row r = zi*35+yi) ----
#define LP_SMEM   (385*35*4)               // 53900 B

// ---------------- helpers ----------------
__device__ __forceinline__ uint32_t smem_u32(const void* p){
    uint32_t a;
    asm("{ .reg .u64 t; cvta.to.shared.u64 t, %1; cvt.u32.u64 %0, t; }"
        : "=r"(a) : "l"(p));
    return a;
}
__device__ __forceinline__ uint32_t swz(uint32_t o){
    return o ^ (((o >> 7) & 7u) << 4);
}

#define CPA16(d,s) asm volatile("cp.async.cg.shared.global [%0], [%1], 16;" :: "r"(d), "l"(s))
#define CPA4(d,s)  asm volatile("cp.async.ca.shared.global [%0], [%1], 4;"  :: "r"(d), "l"(s))
#define CPC()      asm volatile("cp.async.commit_group;")
#define CPW0()     asm volatile("cp.async.wait_group 0;")

#define LDM4(r, a) \
    asm volatile("ldmatrix.sync.aligned.m8n8.x4.shared.b16 {%0,%1,%2,%3}, [%4];" \
        : "=r"((r)[0]),"=r"((r)[1]),"=r"((r)[2]),"=r"((r)[3]) : "r"(a))
#define LDM2(r, a) \
    asm volatile("ldmatrix.sync.aligned.m8n8.x2.shared.b16 {%0,%1}, [%2];" \
        : "=r"((r)[0]),"=r"((r)[1]) : "r"(a))

#define MMAF16(d, a, b0v, b1v) \
    asm volatile("mma.sync.aligned.m16n8k16.row.col.f32.f16.f16.f32 " \
        "{%0,%1,%2,%3}, {%4,%5,%6,%7}, {%8,%9}, {%0,%1,%2,%3};" \
        : "+f"((d)[0]),"+f"((d)[1]),"+f"((d)[2]),"+f"((d)[3]) \
        : "r"((a)[0]),"r"((a)[1]),"r"((a)[2]),"r"((a)[3]), "r"(b0v), "r"(b1v))

// ---------------------------------------------------------------------------
// Weight prep: reorder to K=(ci*128+tap), fp16, pre-apply the XOR swizzle.
// ---------------------------------------------------------------------------
__global__ void prep_kernel(const float* __restrict__ W)
{
    int e = blockIdx.x * 256 + threadIdx.x;   // 144*176*64 = 1,622,016 exact
    int col   = e & 63;
    int row   = (e >> 6) % CO_;
    int chunk = e / (CO_ * KC_);
    int k  = chunk * KC_ + col;
    int ci = k >> 7;
    int tap = k & 127;
    float v = (tap < 125) ? W[((size_t)row * CI_ + ci) * 125 + tap] : 0.f;
    uint32_t off = (uint32_t)(row * 128 + col * 2);
    uint32_t sw  = off ^ ((uint32_t)(row & 7) << 4);
    g_wprep[(size_t)chunk * (CO_ * KC_) + (sw >> 1)] = __float2half_rn(v);
}

__global__ void prep_x_kernel(const float* __restrict__ x)
{
    size_t i = (size_t)blockIdx.x * 256 + threadIdx.x;   // 9,437,184 exact
    g_xh[i] = __float2half_rn(x[i]);
}

// ---------------------------------------------------------------------------
// Main kernel: implicit GEMM + fused gate epilogue.  (round-14 state)
// grid (8 y-tiles, 32 z, 4 b), 256 threads, 2 CTAs/SM. warps 4M x 2N.
// ---------------------------------------------------------------------------
__global__ __launch_bounds__(NT_, 2)
void conv_mma_kernel(const float* __restrict__ sbg, const float* __restrict__ gbg)
{
    extern __shared__ unsigned char smem[];
    const uint32_t smb = smem_u32(smem);

    const int tid = threadIdx.x;
    const int wid = tid >> 5;
    const int lid = tid & 31;
    const int b  = blockIdx.z;
    const int z0 = blockIdx.y;
    const int y0 = blockIdx.x * 4;

    // builder role: 8 warps = 4 y-groups x 2 k-halves (32 k each)
    const int byy = wid & 3, bkh = wid >> 2;
    // mma role: 4 M-groups x 2 N-halves
    const int m0 = (wid >> 1) * 32;
    const int n0 = (wid & 1) * 88;

    __half* xs    = (__half*)(smem + SX_OFF);
    int*   tapoff = (int*)(smem + ST_OFF);
    float* sS     = (float*)(smem + SSB_OFF);
    float* sG     = (float*)(smem + SGB_OFF);

    for (int i = tid; i < XS_VALS; i += NT_) xs[i] = __ushort_as_half(0);
    if (tid < 128) {
        int tap = tid;
        int kd = tap / 25, r = tap % 25;
        int kh = r / 5, kw = r % 5;
        tapoff[tid] = (tap < 125) ? (kd * 8 + kh) * 36 + kw : 1440;
    }
    if (tid < 16) sS[tid] = sbg[tid];
    if (tid < 32) sG[tid] = gbg[tid];
    __syncthreads();

    const __half* xb = g_xh + (size_t)b * CI_ * NSP_;

    auto stage_x = [&](int ci) {
        const __half* xc = xb + (size_t)ci * NSP_;
        for (int it = tid; it < 640; it += NT_) {
            int ck = it & 15;
            int row = it >> 4;           // zi*8 + yi
            int yi = row & 7, zi = row >> 3;
            int gy = y0 + yi - 2, gz = z0 + zi - 2;
            if ((unsigned)gy < 32u && (unsigned)gz < 32u)
                CPA4(smb + SX_OFF + (uint32_t)(row * 36 + 2 + ck * 2) * 2,
                     xc + ((gz * 32 + gy) * 32 + ck * 2));
        }
    };
    auto stage_B = [&](int n, int nb) {
        const char* src = (const char*)g_wprep + (size_t)n * B_TILE;
        uint32_t dst = smb + SB_OFF + nb * B_TILE;
        for (int i = tid; i < B_TILE / 16; i += NT_)
            CPA16(dst + i * 16, src + i * 16);
    };
    auto build_A = [&](int n, int nb) {
        char* Abase = (char*)smem + SA_OFF + nb * A_TILE;
        const int tb  = (n & 1) * 64;
        const int lin = byy * 36 + lid;
        const int m   = byy * 32 + lid;
        const uint32_t mx = (uint32_t)(m & 7) << 4;
#pragma unroll
        for (int j = 0; j < 16; ++j) {
            int k0 = bkh * 32 + 2 * j;
            uint32_t t0 = *(const unsigned short*)((const char*)xs +
                              (uint32_t)(tapoff[tb + k0]     + lin) * 2);
            uint32_t t1 = *(const unsigned short*)((const char*)xs +
                              (uint32_t)(tapoff[tb + k0 + 1] + lin) * 2);
            uint32_t hp = t0 | (t1 << 16);
            *(uint32_t*)(Abase + (((uint32_t)(m * 128 + k0 * 2)) ^ mx)) = hp;
        }
    };

    // lane-invariant ldmatrix offsets
    const uint32_t aLane  = (uint32_t)((lid & 15) * 128 + ((lid & 16) ? 16 : 0));
    const uint32_t bLane4 = (uint32_t)((((lid & 7) + ((lid & 16) ? 8 : 0)) * 128) +
                                       ((lid & 8) ? 16 : 0));
    const uint32_t bLane2 = (uint32_t)((lid & 7) * 128 + ((lid & 8) ? 16 : 0));

    float acc[2][11][4];
#pragma unroll
    for (int mi = 0; mi < 2; ++mi)
#pragma unroll
        for (int ni = 0; ni < 11; ++ni)
#pragma unroll
            for (int r = 0; r < 4; ++r) acc[mi][ni][r] = 0.f;

    // ---- prologue ----
    stage_B(0, 0);
    stage_x(0);
    CPC(); CPW0();
    __syncthreads();
    build_A(0, 0);
    __syncthreads();

    for (int c = 0; c < NCHUNK_; ++c) {
        const int bsel = c & 1;
        if (c + 1 < NCHUNK_) {
            stage_B(c + 1, bsel ^ 1);
            if (((c + 1) & 1) == 0) stage_x((c + 1) >> 1);
            CPC();
        }

        const uint32_t AhB = smb + SA_OFF + bsel * A_TILE;
        const uint32_t BhB = smb + SB_OFF + bsel * B_TILE;

#pragma unroll
        for (int ks = 0; ks < 4; ++ks) {
            const uint32_t kso = (uint32_t)ks * 32;
            uint32_t a0[4], a1[4];
            LDM4(a0, AhB + swz((uint32_t)(m0      * 128) + kso + aLane));
            LDM4(a1, AhB + swz((uint32_t)((m0+16) * 128) + kso + aLane));
#pragma unroll
            for (int nip = 0; nip < 5; ++nip) {
                uint32_t bh[4];
                LDM4(bh, BhB + swz((uint32_t)((n0 + nip * 16) * 128) + kso + bLane4));
                MMAF16(acc[0][nip * 2],     a0, bh[0], bh[1]);
                MMAF16(acc[1][nip * 2],     a1, bh[0], bh[1]);
                MMAF16(acc[0][nip * 2 + 1], a0, bh[2], bh[3]);
                MMAF16(acc[1][nip * 2 + 1], a1, bh[2], bh[3]);
            }
            {   // n-group 10 (cols 80..87)
                uint32_t b2[2];
                LDM2(b2, BhB + swz((uint32_t)((n0 + 80) * 128) + kso + bLane2));
                MMAF16(acc[0][10], a0, b2[0], b2[1]);
                MMAF16(acc[1][10], a1, b2[0], b2[1]);
            }
        }

        if (c + 1 < NCHUNK_) {
            CPW0();
            __syncthreads();
            build_A(c + 1, bsel ^ 1);
        }
        __syncthreads();
    }

    // ---- epilogue: accums -> smem, sigmoid gates, gated write to g_z ----
    float* sD = (float*)smem;   // [176][132] floats = 92928B, reuses tile smem
#pragma unroll
    for (int mi = 0; mi < 2; ++mi)
#pragma unroll
        for (int ni = 0; ni < 11; ++ni)
#pragma unroll
            for (int r = 0; r < 4; ++r) {
                int m  = m0 + mi * 16 + (lid >> 2) + ((r & 2) ? 8 : 0);
                int cc = n0 + ni * 8 + (lid & 3) * 2 + (r & 1);
                sD[cc * 132 + m] = acc[mi][ni][r];
            }
    __syncthreads();

    for (int i = tid; i < 32 * 128; i += NT_) {
        int gi = i >> 7, mm = i & 127;
        int ad = (144 + gi) * 132 + mm;
        sD[ad] = 1.f / (1.f + expf(-(sD[ad] + sG[gi])));
    }
    __syncthreads();

    float* zb = g_z + (size_t)b * NCH_ * NSP_ + (size_t)z0 * 1024 + y0 * 32;
    for (int i = tid; i < 144 * 128; i += NT_) {
        int cc = i >> 7, mm = i & 127;
        float v = sD[cc * 132 + mm];
        float o;
        if (cc < 16) o = fmaxf(v + sS[cc], 0.f);
        else {
            int gi = (cc < 64) ? (cc - 16) / 3 : 16 + (cc - 64) / 5;
            o = v * sD[(144 + gi) * 132 + mm];
        }
        zb[(size_t)cc * NSP_ + mm] = o;
    }
}

// ---------------------------------------------------------------------------
// Depthwise 5^3 gaussian, stride2, pad2 -> (16,16,16). grid (4, 144, 4).
// sZ[385][35] (row r = zi*35+yi, no pad -> 53.9KB, 3-4 CTA/SM).
// Load: fixed-trip unrolled loop, all iterations independent (MLP ~8).
// ---------------------------------------------------------------------------
__global__ __launch_bounds__(256)
void lowpass_kernel(float* __restrict__ out)
{
    extern __shared__ float sZ[];      // [385][35]
    __shared__ float sWg[125];

    const int zt = blockIdx.x;         // 0..3 -> zo0 = 4*zt
    const int c  = blockIdx.y;
    const int b  = blockIdx.z;
    const int tid = threadIdx.x;
    const int wrp = tid >> 5;
    const int lidl = tid & 31;

    if (tid < 125) {
        int kw = tid % 5, t = tid / 5;
        int kh = t % 5,  kd = t / 5;
        double g[5], s = 0.0;
#pragma unroll
        for (int r = 0; r < 5; ++r) {
            double d = (double)(r - 2);
            g[r] = exp(-d * d / 1.5);   // 2*sigma^2 = 1.5
            s += g[r];
        }
        sWg[tid] = (float)(g[kd] * g[kh] * g[kw] / (s * s * s));
    }

    const int zo0 = 4 * zt;
    const int zi0 = 2 * zo0 - 2;       // first input plane
    const float* zc = g_z + (size_t)(b * NCH_ + c) * NSP_;

    // ---- load rows 0..384 (row r -> (zi = r/35, yi = r%35)), independent
    auto load_row = [&](int r) {
        int zi = (r * 937) >> 15;      // exact r/35 for r < 385
        int yi = r - zi * 35;
        int gz = zi0 + zi;
        int gy = yi - 2;
        bool rowok = ((unsigned)gz < 32u) & ((unsigned)gy < 32u);
        const float* rowp = zc + (gz * 32 + gy) * 32;
        float* srow = sZ + r * 35;
        float v = 0.f;
        int gx = lidl - 2;
        if (rowok & ((unsigned)gx < 32u)) v = rowp[gx];
        srow[lidl] = v;
        if (lidl < 3) {
            float v2 = 0.f;
            int gx2 = lidl + 30;
            if (rowok & ((unsigned)gx2 < 32u)) v2 = rowp[gx2];
            srow[32 + lidl] = v2;
        }
    };
#pragma unroll 8
    for (int k = 0; k < 48; ++k) load_row(wrp + 8 * k);
    if (wrp == 0) load_row(384);
    __syncthreads();

    // ---- compute: thread (xo,yo), 4 z-planes; kd-weights in registers
    const int xo = tid & 15;
    const int yo = tid >> 4;
    const float* bp = sZ + (2 * yo) * 35 + 2 * xo;

    float a0 = 0.f, a1 = 0.f, a2 = 0.f, a3 = 0.f;
#pragma unroll
    for (int kh = 0; kh < 5; ++kh) {
#pragma unroll
        for (int kw = 0; kw < 5; ++kw) {
            float w0 = sWg[(0 * 5 + kh) * 5 + kw];
            float w1 = sWg[(1 * 5 + kh) * 5 + kw];
            float w2 = sWg[(2 * 5 + kh) * 5 + kw];
            float w3 = sWg[(3 * 5 + kh) * 5 + kw];
            float w4 = sWg[(4 * 5 + kh) * 5 + kw];
            const int eo = kh * 35 + kw;
#pragma unroll
            for (int p = 0; p < 11; ++p) {
                float v = bp[p * 1225 + eo];
                if (p < 5) {
                    float w = (p == 0) ? w0 : (p == 1) ? w1 : (p == 2) ? w2
                            : (p == 3) ? w3 : w4;
                    a0 += w * v;
                }
                if (p - 2 >= 0 && p - 2 < 5) {
                    int kd = p - 2;
                    float w = (kd == 0) ? w0 : (kd == 1) ? w1 : (kd == 2) ? w2
                            : (kd == 3) ? w3 : w4;
                    a1 += w * v;
                }
                if (p - 4 >= 0 && p - 4 < 5) {
                    int kd = p - 4;
                    float w = (kd == 0) ? w0 : (kd == 1) ? w1 : (kd == 2) ? w2
                            : (kd == 3) ? w3 : w4;
                    a2 += w * v;
                }
                if (p - 6 >= 0) {
                    int kd = p - 6;
                    float w = (kd == 0) ? w0 : (kd == 1) ? w1 : (kd == 2) ? w2
                            : (kd == 3) ? w3 : w4;
                    a3 += w * v;
                }
            }
        }
    }

    float* ob = out + ((size_t)(b * NCH_ + c) * 16 + zo0) * 256 + yo * 16 + xo;
    ob[0]   = a0;
    ob[256] = a1;
    ob[512] = a2;
    ob[768] = a3;
}

// ---------------------------------------------------------------------------
extern "C" void kernel_launch(void* const* d_in, const int* in_sizes, int n_in,
                              void* d_out, int out_size)
{
    const float* x  = (const float*)d_in[0];   // (4,72,32,32,32)
    const float* W  = (const float*)d_in[1];   // (176,72,5,5,5)
    const float* sb = (const float*)d_in[2];   // (16,)
    const float* gb = (const float*)d_in[3];   // (32,)
    float* out = (float*)d_out;                // (4,144,16,16,16)

    cudaFuncSetAttribute(conv_mma_kernel,
                         cudaFuncAttributeMaxDynamicSharedMemorySize, SMEM_TOTAL);
    cudaFuncSetAttribute(lowpass_kernel,
                         cudaFuncAttributeMaxDynamicSharedMemorySize, LP_SMEM);

    prep_kernel<<<6336, 256>>>(W);
    prep_x_kernel<<<36864, 256>>>(x);
    conv_mma_kernel<<<dim3(8, 32, B_), NT_, SMEM_TOTAL>>>(sb, gb);
    lowpass_kernel<<<dim3(4, NCH_, B_), 256, LP_SMEM>>>(out);
}

// round 17
// speedup vs baseline: 1.3587x; 1.0001x over previous
#include <cuda_runtime.h>
#include <cuda_fp16.h>
#include <math.h>
#include <stdint.h>

// ---------------------------------------------------------------------------
// GatedBlock via mma.sync fp16 implicit GEMM (single-term):
//   D = x_f16 * w_f16 ;  conv3d(72->176,k5,pad2) => D[M=128, N=176], K=72*128
//   gate fused into the GEMM epilogue, then depthwise gaussian stride-2.
// Round 16: conv = round-14 state (2 CTA/SM, KC=64). Lowpass: unrolled
//   independent-iteration load (MLP~8), 53.9KB smem (no pad) for 3-4 CTA/SM.
// ---------------------------------------------------------------------------

#define B_      4
#define CI_     72
#define CO_     176
#define NSP_    (32*32*32)
#define NCH_    144

#define KC_     64
#define NCHUNK_ 144           // 72*128 / 64
#define A_TILE  16384         // 128 rows x 64 fp16
#define B_TILE  22528         // 176 rows x 64 fp16
#define NT_     256

__device__ float  g_z[(size_t)B_ * NCH_ * NSP_];
__device__ __half g_wprep[(size_t)NCHUNK_ * CO_ * KC_];  // fp16, pre-swizzled
__device__ __half g_xh[(size_t)B_ * CI_ * NSP_];         // fp16 x image

// ---- smem byte offsets (dynamic smem, conv kernel) ----
// [0, 92928) reused by epilogue sD[176][132]; persistent data above it.
#define SA_OFF    0                        // A: 2 x 16384 = 32768
#define SB_OFF    32768                    // B: 2 x 22528 -> 77824
#define SX_OFF    92928                    // xs: 1584 halves -> 96096
#define XS_VALS   1584
#define ST_OFF    96128                    // tapoff: 128 ints -> 96640
#define SSB_OFF   96640
#define SGB_OFF   96704
#define SMEM_TOTAL 96832

// ---- lowpass: dynamic smem sZ[385][35] floats (row r = zi*35+yi) ----
#define LP_SMEM   (385*35*4)               // 53900 B

// ---------------- helpers ----------------
__device__ __forceinline__ uint32_t smem_u32(const void* p){
    uint32_t a;
    asm("{ .reg .u64 t; cvta.to.shared.u64 t, %1; cvt.u32.u64 %0, t; }"
        : "=r"(a) : "l"(p));
    return a;
}
__device__ __forceinline__ uint32_t swz(uint32_t o){
    return o ^ (((o >> 7) & 7u) << 4);
}

#define CPA16(d,s) asm volatile("cp.async.cg.shared.global [%0], [%1], 16;" :: "r"(d), "l"(s))
#define CPA4(d,s)  asm volatile("cp.async.ca.shared.global [%0], [%1], 4;"  :: "r"(d), "l"(s))
#define CPC()      asm volatile("cp.async.commit_group;")
#define CPW0()     asm volatile("cp.async.wait_group 0;")

#define LDM4(r, a) \
    asm volatile("ldmatrix.sync.aligned.m8n8.x4.shared.b16 {%0,%1,%2,%3}, [%4];" \
        : "=r"((r)[0]),"=r"((r)[1]),"=r"((r)[2]),"=r"((r)[3]) : "r"(a))
#define LDM2(r, a) \
    asm volatile("ldmatrix.sync.aligned.m8n8.x2.shared.b16 {%0,%1}, [%2];" \
        : "=r"((r)[0]),"=r"((r)[1]) : "r"(a))

#define MMAF16(d, a, b0v, b1v) \
    asm volatile("mma.sync.aligned.m16n8k16.row.col.f32.f16.f16.f32 " \
        "{%0,%1,%2,%3}, {%4,%5,%6,%7}, {%8,%9}, {%0,%1,%2,%3};" \
        : "+f"((d)[0]),"+f"((d)[1]),"+f"((d)[2]),"+f"((d)[3]) \
        : "r"((a)[0]),"r"((a)[1]),"r"((a)[2]),"r"((a)[3]), "r"(b0v), "r"(b1v))

// ---------------------------------------------------------------------------
// Weight prep: reorder to K=(ci*128+tap), fp16, pre-apply the XOR swizzle.
// ---------------------------------------------------------------------------
__global__ void prep_kernel(const float* __restrict__ W)
{
    int e = blockIdx.x * 256 + threadIdx.x;   // 144*176*64 = 1,622,016 exact
    int col   = e & 63;
    int row   = (e >> 6) % CO_;
    int chunk = e / (CO_ * KC_);
    int k  = chunk * KC_ + col;
    int ci = k >> 7;
    int tap = k & 127;
    float v = (tap < 125) ? W[((size_t)row * CI_ + ci) * 125 + tap] : 0.f;
    uint32_t off = (uint32_t)(row * 128 + col * 2);
    uint32_t sw  = off ^ ((uint32_t)(row & 7) << 4);
    g_wprep[(size_t)chunk * (CO_ * KC_) + (sw >> 1)] = __float2half_rn(v);
}

__global__ void prep_x_kernel(const float* __restrict__ x)
{
    size_t i = (size_t)blockIdx.x * 256 + threadIdx.x;   // 9,437,184 exact
    g_xh[i] = __float2half_rn(x[i]);
}

// ---------------------------------------------------------------------------
// Main kernel: implicit GEMM + fused gate epilogue.  (round-14 state)
// grid (8 y-tiles, 32 z, 4 b), 256 threads, 2 CTAs/SM. warps 4M x 2N.
// ---------------------------------------------------------------------------
__global__ __launch_bounds__(NT_, 2)
void conv_mma_kernel(const float* __restrict__ sbg, const float* __restrict__ gbg)
{
    extern __shared__ unsigned char smem[];
    const uint32_t smb = smem_u32(smem);

    const int tid = threadIdx.x;
    const int wid = tid >> 5;
    const int lid = tid & 31;
    const int b  = blockIdx.z;
    const int z0 = blockIdx.y;
    const int y0 = blockIdx.x * 4;

    // builder role: 8 warps = 4 y-groups x 2 k-halves (32 k each)
    const int byy = wid & 3, bkh = wid >> 2;
    // mma role: 4 M-groups x 2 N-halves
    const int m0 = (wid >> 1) * 32;
    const int n0 = (wid & 1) * 88;

    __half* xs    = (__half*)(smem + SX_OFF);
    int*   tapoff = (int*)(smem + ST_OFF);
    float* sS     = (float*)(smem + SSB_OFF);
    float* sG     = (float*)(smem + SGB_OFF);

    for (int i = tid; i < XS_VALS; i += NT_) xs[i] = __ushort_as_half(0);
    if (tid < 128) {
        int tap = tid;
        int kd = tap / 25, r = tap % 25;
        int kh = r / 5, kw = r % 5;
        tapoff[tid] = (tap < 125) ? (kd * 8 + kh) * 36 + kw : 1440;
    }
    if (tid < 16) sS[tid] = sbg[tid];
    if (tid < 32) sG[tid] = gbg[tid];
    __syncthreads();

    const __half* xb = g_xh + (size_t)b * CI_ * NSP_;

    auto stage_x = [&](int ci) {
        const __half* xc = xb + (size_t)ci * NSP_;
        for (int it = tid; it < 640; it += NT_) {
            int ck = it & 15;
            int row = it >> 4;           // zi*8 + yi
            int yi = row & 7, zi = row >> 3;
            int gy = y0 + yi - 2, gz = z0 + zi - 2;
            if ((unsigned)gy < 32u && (unsigned)gz < 32u)
                CPA4(smb + SX_OFF + (uint32_t)(row * 36 + 2 + ck * 2) * 2,
                     xc + ((gz * 32 + gy) * 32 + ck * 2));
        }
    };
    auto stage_B = [&](int n, int nb) {
        const char* src = (const char*)g_wprep + (size_t)n * B_TILE;
        uint32_t dst = smb + SB_OFF + nb * B_TILE;
        for (int i = tid; i < B_TILE / 16; i += NT_)
            CPA16(dst + i * 16, src + i * 16);
    };
    auto build_A = [&](int n, int nb) {
        char* Abase = (char*)smem + SA_OFF + nb * A_TILE;
        const int tb  = (n & 1) * 64;
        const int lin = byy * 36 + lid;
        const int m   = byy * 32 + lid;
        const uint32_t mx = (uint32_t)(m & 7) << 4;
#pragma unroll
        for (int j = 0; j < 16; ++j) {
            int k0 = bkh * 32 + 2 * j;
            uint32_t t0 = *(const unsigned short*)((const char*)xs +
                              (uint32_t)(tapoff[tb + k0]     + lin) * 2);
            uint32_t t1 = *(const unsigned short*)((const char*)xs +
                              (uint32_t)(tapoff[tb + k0 + 1] + lin) * 2);
            uint32_t hp = t0 | (t1 << 16);
            *(uint32_t*)(Abase + (((uint32_t)(m * 128 + k0 * 2)) ^ mx)) = hp;
        }
    };

    // lane-invariant ldmatrix offsets
    const uint32_t aLane  = (uint32_t)((lid & 15) * 128 + ((lid & 16) ? 16 : 0));
    const uint32_t bLane4 = (uint32_t)((((lid & 7) + ((lid & 16) ? 8 : 0)) * 128) +
                                       ((lid & 8) ? 16 : 0));
    const uint32_t bLane2 = (uint32_t)((lid & 7) * 128 + ((lid & 8) ? 16 : 0));

    float acc[2][11][4];
#pragma unroll
    for (int mi = 0; mi < 2; ++mi)
#pragma unroll
        for (int ni = 0; ni < 11; ++ni)
#pragma unroll
            for (int r = 0; r < 4; ++r) acc[mi][ni][r] = 0.f;

    // ---- prologue ----
    stage_B(0, 0);
    stage_x(0);
    CPC(); CPW0();
    __syncthreads();
    build_A(0, 0);
    __syncthreads();

    for (int c = 0; c < NCHUNK_; ++c) {
        const int bsel = c & 1;
        if (c + 1 < NCHUNK_) {
            stage_B(c + 1, bsel ^ 1);
            if (((c + 1) & 1) == 0) stage_x((c + 1) >> 1);
            CPC();
        }

        const uint32_t AhB = smb + SA_OFF + bsel * A_TILE;
        const uint32_t BhB = smb + SB_OFF + bsel * B_TILE;

#pragma unroll
        for (int ks = 0; ks < 4; ++ks) {
            const uint32_t kso = (uint32_t)ks * 32;
            uint32_t a0[4], a1[4];
            LDM4(a0, AhB + swz((uint32_t)(m0      * 128) + kso + aLane));
            LDM4(a1, AhB + swz((uint32_t)((m0+16) * 128) + kso + aLane));
#pragma unroll
            for (int nip = 0; nip < 5; ++nip) {
                uint32_t bh[4];
                LDM4(bh, BhB + swz((uint32_t)((n0 + nip * 16) * 128) + kso + bLane4));
                MMAF16(acc[0][nip * 2],     a0, bh[0], bh[1]);
                MMAF16(acc[1][nip * 2],     a1, bh[0], bh[1]);
                MMAF16(acc[0][nip * 2 + 1], a0, bh[2], bh[3]);
                MMAF16(acc[1][nip * 2 + 1], a1, bh[2], bh[3]);
            }
            {   // n-group 10 (cols 80..87)
                uint32_t b2[2];
                LDM2(b2, BhB + swz((uint32_t)((n0 + 80) * 128) + kso + bLane2));
                MMAF16(acc[0][10], a0, b2[0], b2[1]);
                MMAF16(acc[1][10], a1, b2[0], b2[1]);
            }
        }

        if (c + 1 < NCHUNK_) {
            CPW0();
            __syncthreads();
            build_A(c + 1, bsel ^ 1);
        }
        __syncthreads();
    }

    // ---- epilogue: accums -> smem, sigmoid gates, gated write to g_z ----
    float* sD = (float*)smem;   // [176][132] floats = 92928B, reuses tile smem
#pragma unroll
    for (int mi = 0; mi < 2; ++mi)
#pragma unroll
        for (int ni = 0; ni < 11; ++ni)
#pragma unroll
            for (int r = 0; r < 4; ++r) {
                int m  = m0 + mi * 16 + (lid >> 2) + ((r & 2) ? 8 : 0);
                int cc = n0 + ni * 8 + (lid & 3) * 2 + (r & 1);
                sD[cc * 132 + m] = acc[mi][ni][r];
            }
    __syncthreads();

    for (int i = tid; i < 32 * 128; i += NT_) {
        int gi = i >> 7, mm = i & 127;
        int ad = (144 + gi) * 132 + mm;
        sD[ad] = 1.f / (1.f + expf(-(sD[ad] + sG[gi])));
    }
    __syncthreads();

    float* zb = g_z + (size_t)b * NCH_ * NSP_ + (size_t)z0 * 1024 + y0 * 32;
    for (int i = tid; i < 144 * 128; i += NT_) {
        int cc = i >> 7, mm = i & 127;
        float v = sD[cc * 132 + mm];
        float o;
        if (cc < 16) o = fmaxf(v + sS[cc], 0.f);
        else {
            int gi = (cc < 64) ? (cc - 16) / 3 : 16 + (cc - 64) / 5;
            o = v * sD[(144 + gi) * 132 + mm];
        }
        zb[(size_t)cc * NSP_ + mm] = o;
    }
}

// ---------------------------------------------------------------------------
// Depthwise 5^3 gaussian, stride2, pad2 -> (16,16,16). grid (4, 144, 4).
// sZ[385][35] (row r = zi*35+yi, no pad -> 53.9KB, 3-4 CTA/SM).
// Load: fixed-trip unrolled loop, all iterations independent (MLP ~8).
// ---------------------------------------------------------------------------
__global__ __launch_bounds__(256)
void lowpass_kernel(float* __restrict__ out)
{
    extern __shared__ float sZ[];      // [385][35]
    __shared__ float sWg[125];

    const int zt = blockIdx.x;         // 0..3 -> zo0 = 4*zt
    const int c  = blockIdx.y;
    const int b  = blockIdx.z;
    const int tid = threadIdx.x;
    const int wrp = tid >> 5;
    const int lidl = tid & 31;

    if (tid < 125) {
        int kw = tid % 5, t = tid / 5;
        int kh = t % 5,  kd = t / 5;
        double g[5], s = 0.0;
#pragma unroll
        for (int r = 0; r < 5; ++r) {
            double d = (double)(r - 2);
            g[r] = exp(-d * d / 1.5);   // 2*sigma^2 = 1.5
            s += g[r];
        }
        sWg[tid] = (float)(g[kd] * g[kh] * g[kw] / (s * s * s));
    }

    const int zo0 = 4 * zt;
    const int zi0 = 2 * zo0 - 2;       // first input plane
    const float* zc = g_z + (size_t)(b * NCH_ + c) * NSP_;

    // ---- load rows 0..384 (row r -> (zi = r/35, yi = r%35)), independent
    auto load_row = [&](int r) {
        int zi = (r * 937) >> 15;      // exact r/35 for r < 385
        int yi = r - zi * 35;
        int gz = zi0 + zi;
        int gy = yi - 2;
        bool rowok = ((unsigned)gz < 32u) & ((unsigned)gy < 32u);
        const float* rowp = zc + (gz * 32 + gy) * 32;
        float* srow = sZ + r * 35;
        float v = 0.f;
        int gx = lidl - 2;
        if (rowok & ((unsigned)gx < 32u)) v = rowp[gx];
        srow[lidl] = v;
        if (lidl < 3) {
            float v2 = 0.f;
            int gx2 = lidl + 30;
            if (rowok & ((unsigned)gx2 < 32u)) v2 = rowp[gx2];
            srow[32 + lidl] = v2;
        }
    };
#pragma unroll 8
    for (int k = 0; k < 48; ++k) load_row(wrp + 8 * k);
    if (wrp == 0) load_row(384);
    __syncthreads();

    // ---- compute: thread (xo,yo), 4 z-planes; kd-weights in registers
    const int xo = tid & 15;
    const int yo = tid >> 4;
    const float* bp = sZ + (2 * yo) * 35 + 2 * xo;

    float a0 = 0.f, a1 = 0.f, a2 = 0.f, a3 = 0.f;
#pragma unroll
    for (int kh = 0; kh < 5; ++kh) {
#pragma unroll
        for (int kw = 0; kw < 5; ++kw) {
            float w0 = sWg[(0 * 5 + kh) * 5 + kw];
            float w1 = sWg[(1 * 5 + kh) * 5 + kw];
            float w2 = sWg[(2 * 5 + kh) * 5 + kw];
            float w3 = sWg[(3 * 5 + kh) * 5 + kw];
            float w4 = sWg[(4 * 5 + kh) * 5 + kw];
            const int eo = kh * 35 + kw;
#pragma unroll
            for (int p = 0; p < 11; ++p) {
                float v = bp[p * 1225 + eo];
                if (p < 5) {
                    float w = (p == 0) ? w0 : (p == 1) ? w1 : (p == 2) ? w2
                            : (p == 3) ? w3 : w4;
                    a0 += w * v;
                }
                if (p - 2 >= 0 && p - 2 < 5) {
                    int kd = p - 2;
                    float w = (kd == 0) ? w0 : (kd == 1) ? w1 : (kd == 2) ? w2
                            : (kd == 3) ? w3 : w4;
                    a1 += w * v;
                }
                if (p - 4 >= 0 && p - 4 < 5) {
                    int kd = p - 4;
                    float w = (kd == 0) ? w0 : (kd == 1) ? w1 : (kd == 2) ? w2
                            : (kd == 3) ? w3 : w4;
                    a2 += w * v;
                }
                if (p - 6 >= 0) {
                    int kd = p - 6;
                    float w = (kd == 0) ? w0 : (kd == 1) ? w1 : (kd == 2) ? w2
                            : (kd == 3) ? w3 : w4;
                    a3 += w * v;
                }
            }
        }
    }

    float* ob = out + ((size_t)(b * NCH_ + c) * 16 + zo0) * 256 + yo * 16 + xo;
    ob[0]   = a0;
    ob[256] = a1;
    ob[512] = a2;
    ob[768] = a3;
}

// ---------------------------------------------------------------------------
extern "C" void kernel_launch(void* const* d_in, const int* in_sizes, int n_in,
                              void* d_out, int out_size)
{
    const float* x  = (const float*)d_in[0];   // (4,72,32,32,32)
    const float* W  = (const float*)d_in[1];   // (176,72,5,5,5)
    const float* sb = (const float*)d_in[2];   // (16,)
    const float* gb = (const float*)d_in[3];   // (32,)
    float* out = (float*)d_out;                // (4,144,16,16,16)

    cudaFuncSetAttribute(conv_mma_kernel,
                         cudaFuncAttributeMaxDynamicSharedMemorySize, SMEM_TOTAL);
    cudaFuncSetAttribute(lowpass_kernel,
                         cudaFuncAttributeMaxDynamicSharedMemorySize, LP_SMEM);

    prep_kernel<<<6336, 256>>>(W);
    prep_x_kernel<<<36864, 256>>>(x);
    conv_mma_kernel<<<dim3(8, 32, B_), NT_, SMEM_TOTAL>>>(sb, gb);
    lowpass_kernel<<<dim3(4, NCH_, B_), 256, LP_SMEM>>>(out);
}